// round 10
// baseline (speedup 1.0000x reference)
#include <cuda_runtime.h>
#include <cuda_bf16.h>
#include <cstdint>

#define N_NODES 16384
#define D       128
#define R_T     5
#define H_H     4
#define E_EDGES 262144
#define MAXDEG  128   // Poisson(16) tail: P(deg>=128) ~ 1e-60

typedef unsigned long long u64;

// ---------------- device scratch (static globals; no allocation) ----------------
__device__ float g_K[R_T * N_NODES * D];      // 41.9 MB
__device__ float g_Q[R_T * N_NODES * D];      // 41.9 MB
__device__ float g_V[R_T * N_NODES * D];      // 41.9 MB
__device__ float g_agg[N_NODES * 512];        // 33.5MB [N][H*D]
__device__ int   g_cursor[N_NODES];           // zero-init; agg resets each replay
__device__ int   g_e_idx[N_NODES * MAXDEG];   // padded CSR: r*N + src
__device__ float4 g_e_score[N_NODES * MAXDEG];// padded CSR: exp(score) per head

// ---------------- helpers ----------------
__device__ __forceinline__ uint32_t f2tf32(float x) {
    uint32_t r;
    asm("cvt.rna.tf32.f32 %0, %1;" : "=r"(r) : "f"(x));
    return r;
}
__device__ __forceinline__ void mma_tf32(float d[4], const uint32_t a[4],
                                         uint32_t b0, uint32_t b1) {
    asm volatile(
        "mma.sync.aligned.m16n8k8.row.col.f32.tf32.tf32.f32 "
        "{%0,%1,%2,%3}, {%4,%5,%6,%7}, {%8,%9}, {%0,%1,%2,%3};"
        : "+f"(d[0]), "+f"(d[1]), "+f"(d[2]), "+f"(d[3])
        : "r"(a[0]), "r"(a[1]), "r"(a[2]), "r"(a[3]), "r"(b0), "r"(b1));
}

// ---- shared tc-GEMM fragment machinery (verified R7/R8) ----
__device__ __forceinline__ void stage_A(
    float* h_s, const float4* __restrict__ src4, int rowStride4, int rowBase,
    int colq0, int tid)
{
    for (int idx = tid; idx < 4096; idx += 512) {
        int n  = idx >> 5;
        int kq = idx & 31;
        float4 v = src4[(size_t)(rowBase + n) * rowStride4 + colq0 + kq];
        uint4 t;
        t.x = f2tf32(v.x); t.y = f2tf32(v.y);
        t.z = f2tf32(v.z); t.w = f2tf32(v.w);
        *(uint4*)(h_s + n * 128 + ((kq * 4) ^ ((n & 7) << 2))) = t;
    }
}

__device__ __forceinline__ void stage_B(
    float* w_s, const float4* __restrict__ W4, int kBase, int tid)
{
    for (int idx = tid; idx < 4096; idx += 512) {
        int k  = idx >> 5;
        int cq = idx & 31;
        float4 v = W4[(size_t)(kBase + k) * 32 + cq];
        uint4 t;
        t.x = f2tf32(v.x); t.y = f2tf32(v.y);
        t.z = f2tf32(v.z); t.w = f2tf32(v.w);
        *(uint4*)(w_s + k * 128 + ((cq * 4) ^ ((k & 3) << 3))) = t;
    }
}

__device__ __forceinline__ void mma_tile(
    const uint32_t* __restrict__ hsu, const uint32_t* __restrict__ wsu,
    int nA, int xrA, int cbase, int gid, int tig, float acc[8][4])
{
    #pragma unroll 4
    for (int ks = 0; ks < 16; ks++) {
        int k0 = ks * 8 + tig;
        int ka  = k0 ^ xrA;
        int ka4 = (k0 + 4) ^ xrA;
        uint32_t a[4];
        a[0] = hsu[(nA    ) * 128 + ka ];
        a[1] = hsu[(nA + 8) * 128 + ka ];
        a[2] = hsu[(nA    ) * 128 + ka4];
        a[3] = hsu[(nA + 8) * 128 + ka4];
        #pragma unroll
        for (int nt = 0; nt < 8; nt++) {
            int cs = (cbase + nt * 8 + gid) ^ (tig << 3);
            uint32_t b0 = wsu[ k0      * 128 + cs];
            uint32_t b1 = wsu[(k0 + 4) * 128 + cs];
            mma_tf32(acc[nt], a, b0, b1);
        }
    }
}

__global__ void dummy_kernel() {}

// Tensor-core QKV: grid (N/128, R), 512 threads, 128 KB dyn smem.
__global__ void __launch_bounds__(512) qkv_gemm_tc(
    const float* __restrict__ h,
    const float* __restrict__ Wk, const float* __restrict__ bk,
    const float* __restrict__ Wq, const float* __restrict__ bq,
    const float* __restrict__ Wv, const float* __restrict__ bv)
{
    extern __shared__ float smem[];
    float* h_s = smem;            // 128 x 128 tf32 (64 KB)
    float* w_s = smem + 16384;    // 128 x 128 tf32 (64 KB)

    int r = blockIdx.y;
    int nodeBase = blockIdx.x * 128;
    int tid = threadIdx.x;

    stage_A(h_s, (const float4*)h, 32, nodeBase, 0, tid);

    int lane = tid & 31, wid = tid >> 5;
    int gid = lane >> 2, tig = lane & 3;
    int wrow = wid & 7, wcol = wid >> 3;
    int cbase = wcol * 64;
    int nA = wrow * 16 + gid;
    int xrA = gid << 2;

    const uint32_t* hsu = (const uint32_t*)h_s;
    const uint32_t* wsu = (const uint32_t*)w_s;

    #pragma unroll 1
    for (int which = 0; which < 3; which++) {
        const float* W; const float* b; float* out;
        if (which == 0)      { W = Wk; b = bk; out = g_K; }
        else if (which == 1) { W = Wq; b = bq; out = g_Q; }
        else                 { W = Wv; b = bv; out = g_V; }
        W += r * D * D;
        b += r * D;
        out += (size_t)r * N_NODES * D;

        __syncthreads();
        stage_B(w_s, (const float4*)W, 0, tid);
        __syncthreads();

        float acc[8][4];
        #pragma unroll
        for (int nt = 0; nt < 8; nt++) {
            float2 bv2 = *(const float2*)(b + cbase + nt * 8 + 2 * tig);
            acc[nt][0] = bv2.x; acc[nt][1] = bv2.y;
            acc[nt][2] = bv2.x; acc[nt][3] = bv2.y;
        }

        mma_tile(hsu, wsu, nA, xrA, cbase, gid, tig, acc);

        int row0 = nodeBase + wrow * 16 + gid;
        #pragma unroll
        for (int nt = 0; nt < 8; nt++) {
            int col0 = cbase + nt * 8 + 2 * tig;
            *(float2*)(out + (size_t)row0 * D + col0) =
                make_float2(acc[nt][0], acc[nt][1]);
            *(float2*)(out + (size_t)(row0 + 8) * D + col0) =
                make_float2(acc[nt][2], acc[nt][3]);
        }
    }
}

// Per-edge attention scores: warp per edge, exp(score) + direct padded-CSR write.
__global__ void __launch_bounds__(256) score_kernel(
    const int* __restrict__ src, const int* __restrict__ dst,
    const int* __restrict__ etype)
{
    int e = blockIdx.x * 8 + (threadIdx.x >> 5);
    int lane = threadIdx.x & 31;
    int r = etype[e];
    int s = src[e];
    int dn = dst[e];
    const float4* kp = (const float4*)(g_K + ((size_t)r * N_NODES + s)  * D);
    const float4* qp = (const float4*)(g_Q + ((size_t)r * N_NODES + dn) * D);
    float4 k4 = kp[lane];
    float4 q4 = qp[lane];
    float p = k4.x * q4.x + k4.y * q4.y + k4.z * q4.z + k4.w * q4.w;
    p += __shfl_xor_sync(0xffffffff, p, 1);
    p += __shfl_xor_sync(0xffffffff, p, 2);
    p += __shfl_xor_sync(0xffffffff, p, 4);
    float ex = __expf(p * 0.1767766952966369f);   // head value at lanes 0,8,16,24
    float e0 = __shfl_sync(0xffffffff, ex, 0);
    float e1 = __shfl_sync(0xffffffff, ex, 8);
    float e2 = __shfl_sync(0xffffffff, ex, 16);
    float e3 = __shfl_sync(0xffffffff, ex, 24);
    if (lane == 0) {
        int pos = atomicAdd(&g_cursor[dn], 1);
        if (pos < MAXDEG) {
            int slot = (dn << 7) + pos;
            g_e_idx[slot] = r * N_NODES + s;
            g_e_score[slot] = make_float4(e0, e1, e2, e3);
        }
    }
}

// Per-destination-node softmax + weighted aggregation. Block (128 thr) per node.
// Denominator on warp 0 only; V-gather unrolled x4 for MLP.
__global__ void __launch_bounds__(128) agg_kernel()
{
    int n = blockIdx.x;
    int tid = threadIdx.x;
    int deg = min(g_cursor[n], MAXDEG);
    int base = n << 7;

    __shared__ float s_den[R_T * H_H];
    __shared__ float s_inv[R_T * H_H];
    __shared__ int    s_i[32];
    __shared__ float4 s_a[32];

    if (tid < R_T * H_H) s_den[tid] = 0.f;
    __syncthreads();
    if (tid == 0) g_cursor[n] = 0;   // reset for next replay (deg already read)

    // denominator: single warp (deg ~16), shared atomics
    if (tid < 32) {
        for (int j = tid; j < deg; j += 32) {
            int r = g_e_idx[base + j] >> 14;        // N = 2^14
            float4 sc = g_e_score[base + j];
            atomicAdd(&s_den[r * 4 + 0], sc.x);
            atomicAdd(&s_den[r * 4 + 1], sc.y);
            atomicAdd(&s_den[r * 4 + 2], sc.z);
            atomicAdd(&s_den[r * 4 + 3], sc.w);
        }
    }
    __syncthreads();
    if (tid < R_T * H_H) s_inv[tid] = 1.0f / s_den[tid];
    __syncthreads();

    float a0 = 0.f, a1 = 0.f, a2 = 0.f, a3 = 0.f;
    for (int j0 = 0; j0 < deg; j0 += 32) {
        int m = min(32, deg - j0);
        if (tid < m) {
            int idx = g_e_idx[base + j0 + tid];
            int r = idx >> 14;
            float4 sc = g_e_score[base + j0 + tid];
            float4 a;
            a.x = sc.x * s_inv[r * 4 + 0];
            a.y = sc.y * s_inv[r * 4 + 1];
            a.z = sc.z * s_inv[r * 4 + 2];
            a.w = sc.w * s_inv[r * 4 + 3];
            s_a[tid] = a;
            s_i[tid] = idx;
        }
        __syncthreads();

        int jj = 0;
        for (; jj + 4 <= m; jj += 4) {
            int v0 = s_i[jj], v1 = s_i[jj + 1], v2 = s_i[jj + 2], v3 = s_i[jj + 3];
            float f0 = g_V[(size_t)v0 * D + tid];
            float f1 = g_V[(size_t)v1 * D + tid];
            float f2 = g_V[(size_t)v2 * D + tid];
            float f3 = g_V[(size_t)v3 * D + tid];
            float4 w0 = s_a[jj], w1 = s_a[jj + 1], w2 = s_a[jj + 2], w3 = s_a[jj + 3];
            a0 += w0.x * f0 + w1.x * f1 + w2.x * f2 + w3.x * f3;
            a1 += w0.y * f0 + w1.y * f1 + w2.y * f2 + w3.y * f3;
            a2 += w0.z * f0 + w1.z * f1 + w2.z * f2 + w3.z * f3;
            a3 += w0.w * f0 + w1.w * f1 + w2.w * f2 + w3.w * f3;
        }
        for (; jj < m; jj++) {
            int vrow = s_i[jj];
            float4 a = s_a[jj];
            float v = g_V[(size_t)vrow * D + tid];
            a0 += a.x * v; a1 += a.y * v; a2 += a.z * v; a3 += a.w * v;
        }
        __syncthreads();
    }

    float* o = g_agg + (size_t)n * 512;
    o[tid]       = a0;
    o[128 + tid] = a1;
    o[256 + tid] = a2;
    o[384 + tid] = a3;
}

// Final projection (tensor-core): out[N,128] = g_agg[N,512] @ Wt[512,128] + bt.
__global__ void __launch_bounds__(512) final_gemm_tc(
    const float* __restrict__ Wt, const float* __restrict__ bt,
    float* __restrict__ out)
{
    extern __shared__ float smem[];
    float* h_s = smem;
    float* w_s = smem + 16384;

    int nodeBase = blockIdx.x * 128;
    int tid = threadIdx.x;
    int lane = tid & 31, wid = tid >> 5;
    int gid = lane >> 2, tig = lane & 3;
    int wrow = wid & 7, wcol = wid >> 3;
    int cbase = wcol * 64;
    int nA = wrow * 16 + gid;
    int xrA = gid << 2;

    const uint32_t* hsu = (const uint32_t*)h_s;
    const uint32_t* wsu = (const uint32_t*)w_s;

    float acc[8][4];
    #pragma unroll
    for (int nt = 0; nt < 8; nt++) {
        float2 bv2 = *(const float2*)(bt + cbase + nt * 8 + 2 * tig);
        acc[nt][0] = bv2.x; acc[nt][1] = bv2.y;
        acc[nt][2] = bv2.x; acc[nt][3] = bv2.y;
    }

    #pragma unroll 1
    for (int kb = 0; kb < 4; kb++) {
        __syncthreads();
        stage_A(h_s, (const float4*)g_agg, 128, nodeBase, kb * 32, tid);
        stage_B(w_s, (const float4*)Wt, kb * 128, tid);
        __syncthreads();
        mma_tile(hsu, wsu, nA, xrA, cbase, gid, tig, acc);
    }

    int row0 = nodeBase + wrow * 16 + gid;
    #pragma unroll
    for (int nt = 0; nt < 8; nt++) {
        int col0 = cbase + nt * 8 + 2 * tig;
        *(float2*)(out + (size_t)row0 * D + col0) =
            make_float2(acc[nt][0], acc[nt][1]);
        *(float2*)(out + (size_t)(row0 + 8) * D + col0) =
            make_float2(acc[nt][2], acc[nt][3]);
    }
}

// ---------------- launch ----------------
extern "C" void kernel_launch(void* const* d_in, const int* in_sizes, int n_in,
                              void* d_out, int out_size)
{
    const float* h  = (const float*)d_in[0];
    const float* Wk = (const float*)d_in[1];
    const float* bk = (const float*)d_in[2];
    const float* Wq = (const float*)d_in[3];
    const float* bq = (const float*)d_in[4];
    const float* Wv = (const float*)d_in[5];
    const float* bv = (const float*)d_in[6];
    const float* Wt = (const float*)d_in[7];
    const float* bt = (const float*)d_in[8];
    const int* src   = (const int*)d_in[9];
    const int* dst   = (const int*)d_in[10];
    const int* etype = (const int*)d_in[11];
    float* out = (float*)d_out;

    const int TC_SMEM = 2 * 128 * 128 * 4;  // 128 KB dynamic
    cudaFuncSetAttribute(qkv_gemm_tc,
                         cudaFuncAttributeMaxDynamicSharedMemorySize, TC_SMEM);
    cudaFuncSetAttribute(final_gemm_tc,
                         cudaFuncAttributeMaxDynamicSharedMemorySize, TC_SMEM);

    qkv_gemm_tc<<<dim3(N_NODES / 128, R_T), 512, TC_SMEM>>>(h, Wk, bk, Wq, bq, Wv, bv); // 1
    dummy_kernel<<<1, 32>>>();                                    // 2
    dummy_kernel<<<1, 32>>>();                                    // 3
    score_kernel<<<E_EDGES / 8, 256>>>(src, dst, etype);          // 4 (profiled)
    agg_kernel<<<N_NODES, 128>>>();                               // 5
    final_gemm_tc<<<N_NODES / 128, 512, TC_SMEM>>>(Wt, bt, out);  // 6
}

// round 11
// speedup vs baseline: 1.1906x; 1.1906x over previous
#include <cuda_runtime.h>
#include <cuda_bf16.h>
#include <cstdint>

#define N_NODES 16384
#define D       128
#define R_T     5
#define H_H     4
#define E_EDGES 262144
#define MAXDEG  128   // Poisson(16) tail: P(deg>=128) ~ 1e-60

typedef unsigned long long u64;

// ---------------- device scratch (static globals; no allocation) ----------------
__device__ float g_K[R_T * N_NODES * D];      // 41.9 MB
__device__ float g_Q[R_T * N_NODES * D];      // 41.9 MB
__device__ float g_V[R_T * N_NODES * D];      // 41.9 MB
__device__ float g_agg[N_NODES * 512];        // 33.5MB [N][H*D]
__device__ int   g_cursor[N_NODES];           // zero-init; agg resets each replay
__device__ int   g_e_idx[N_NODES * MAXDEG];   // padded CSR: r*N + src
__device__ float4 g_e_score[N_NODES * MAXDEG];// padded CSR: exp(score) per head

// ---------------- helpers ----------------
__device__ __forceinline__ uint32_t f2tf32(float x) {
    uint32_t r;
    asm("cvt.rna.tf32.f32 %0, %1;" : "=r"(r) : "f"(x));
    return r;
}
__device__ __forceinline__ void mma_tf32(float d[4], const uint32_t a[4],
                                         uint32_t b0, uint32_t b1) {
    asm volatile(
        "mma.sync.aligned.m16n8k8.row.col.f32.tf32.tf32.f32 "
        "{%0,%1,%2,%3}, {%4,%5,%6,%7}, {%8,%9}, {%0,%1,%2,%3};"
        : "+f"(d[0]), "+f"(d[1]), "+f"(d[2]), "+f"(d[3])
        : "r"(a[0]), "r"(a[1]), "r"(a[2]), "r"(a[3]), "r"(b0), "r"(b1));
}

// ---- shared tc-GEMM fragment machinery (verified R7/R8) ----
__device__ __forceinline__ void stage_A(
    float* h_s, const float4* __restrict__ src4, int rowStride4, int rowBase,
    int colq0, int tid)
{
    for (int idx = tid; idx < 4096; idx += 512) {
        int n  = idx >> 5;
        int kq = idx & 31;
        float4 v = src4[(size_t)(rowBase + n) * rowStride4 + colq0 + kq];
        uint4 t;
        t.x = f2tf32(v.x); t.y = f2tf32(v.y);
        t.z = f2tf32(v.z); t.w = f2tf32(v.w);
        *(uint4*)(h_s + n * 128 + ((kq * 4) ^ ((n & 7) << 2))) = t;
    }
}

__device__ __forceinline__ void stage_B(
    float* w_s, const float4* __restrict__ W4, int kBase, int tid)
{
    for (int idx = tid; idx < 4096; idx += 512) {
        int k  = idx >> 5;
        int cq = idx & 31;
        float4 v = W4[(size_t)(kBase + k) * 32 + cq];
        uint4 t;
        t.x = f2tf32(v.x); t.y = f2tf32(v.y);
        t.z = f2tf32(v.z); t.w = f2tf32(v.w);
        *(uint4*)(w_s + k * 128 + ((cq * 4) ^ ((k & 3) << 3))) = t;
    }
}

__device__ __forceinline__ void mma_tile(
    const uint32_t* __restrict__ hsu, const uint32_t* __restrict__ wsu,
    int nA, int xrA, int cbase, int gid, int tig, float acc[8][4])
{
    #pragma unroll 4
    for (int ks = 0; ks < 16; ks++) {
        int k0 = ks * 8 + tig;
        int ka  = k0 ^ xrA;
        int ka4 = (k0 + 4) ^ xrA;
        uint32_t a[4];
        a[0] = hsu[(nA    ) * 128 + ka ];
        a[1] = hsu[(nA + 8) * 128 + ka ];
        a[2] = hsu[(nA    ) * 128 + ka4];
        a[3] = hsu[(nA + 8) * 128 + ka4];
        #pragma unroll
        for (int nt = 0; nt < 8; nt++) {
            int cs = (cbase + nt * 8 + gid) ^ (tig << 3);
            uint32_t b0 = wsu[ k0      * 128 + cs];
            uint32_t b1 = wsu[(k0 + 4) * 128 + cs];
            mma_tf32(acc[nt], a, b0, b1);
        }
    }
}

// Tensor-core QKV: grid (N/128, R), 512 threads, 128 KB dyn smem.
__global__ void __launch_bounds__(512) qkv_gemm_tc(
    const float* __restrict__ h,
    const float* __restrict__ Wk, const float* __restrict__ bk,
    const float* __restrict__ Wq, const float* __restrict__ bq,
    const float* __restrict__ Wv, const float* __restrict__ bv)
{
    extern __shared__ float smem[];
    float* h_s = smem;            // 128 x 128 tf32 (64 KB)
    float* w_s = smem + 16384;    // 128 x 128 tf32 (64 KB)

    int r = blockIdx.y;
    int nodeBase = blockIdx.x * 128;
    int tid = threadIdx.x;

    stage_A(h_s, (const float4*)h, 32, nodeBase, 0, tid);

    int lane = tid & 31, wid = tid >> 5;
    int gid = lane >> 2, tig = lane & 3;
    int wrow = wid & 7, wcol = wid >> 3;
    int cbase = wcol * 64;
    int nA = wrow * 16 + gid;
    int xrA = gid << 2;

    const uint32_t* hsu = (const uint32_t*)h_s;
    const uint32_t* wsu = (const uint32_t*)w_s;

    #pragma unroll 1
    for (int which = 0; which < 3; which++) {
        const float* W; const float* b; float* out;
        if (which == 0)      { W = Wk; b = bk; out = g_K; }
        else if (which == 1) { W = Wq; b = bq; out = g_Q; }
        else                 { W = Wv; b = bv; out = g_V; }
        W += r * D * D;
        b += r * D;
        out += (size_t)r * N_NODES * D;

        __syncthreads();
        stage_B(w_s, (const float4*)W, 0, tid);
        __syncthreads();

        float acc[8][4];
        #pragma unroll
        for (int nt = 0; nt < 8; nt++) {
            float2 bv2 = *(const float2*)(b + cbase + nt * 8 + 2 * tig);
            acc[nt][0] = bv2.x; acc[nt][1] = bv2.y;
            acc[nt][2] = bv2.x; acc[nt][3] = bv2.y;
        }

        mma_tile(hsu, wsu, nA, xrA, cbase, gid, tig, acc);

        int row0 = nodeBase + wrow * 16 + gid;
        #pragma unroll
        for (int nt = 0; nt < 8; nt++) {
            int col0 = cbase + nt * 8 + 2 * tig;
            *(float2*)(out + (size_t)row0 * D + col0) =
                make_float2(acc[nt][0], acc[nt][1]);
            *(float2*)(out + (size_t)(row0 + 8) * D + col0) =
                make_float2(acc[nt][2], acc[nt][3]);
        }
    }
}

// Per-edge attention scores: 2 edges per warp (consecutive), 4 LDG.128 in
// flight per lane (MLP 4). exp(score) + direct padded-CSR payload write.
__global__ void __launch_bounds__(256) score_kernel(
    const int* __restrict__ src, const int* __restrict__ dst,
    const int* __restrict__ etype)
{
    int wid = threadIdx.x >> 5;
    int lane = threadIdx.x & 31;
    int e0 = blockIdx.x * 16 + wid * 2;          // e0 even -> int2 aligned

    int2 ss = *(const int2*)(src + e0);
    int2 dd = *(const int2*)(dst + e0);
    int2 rr = *(const int2*)(etype + e0);

    const float4* k0p = (const float4*)(g_K + ((size_t)rr.x * N_NODES + ss.x) * D);
    const float4* q0p = (const float4*)(g_Q + ((size_t)rr.x * N_NODES + dd.x) * D);
    const float4* k1p = (const float4*)(g_K + ((size_t)rr.y * N_NODES + ss.y) * D);
    const float4* q1p = (const float4*)(g_Q + ((size_t)rr.y * N_NODES + dd.y) * D);
    float4 k0 = k0p[lane];
    float4 q0 = q0p[lane];
    float4 k1 = k1p[lane];
    float4 q1 = q1p[lane];

    float p0 = k0.x * q0.x + k0.y * q0.y + k0.z * q0.z + k0.w * q0.w;
    float p1 = k1.x * q1.x + k1.y * q1.y + k1.z * q1.z + k1.w * q1.w;
    p0 += __shfl_xor_sync(0xffffffff, p0, 1);
    p1 += __shfl_xor_sync(0xffffffff, p1, 1);
    p0 += __shfl_xor_sync(0xffffffff, p0, 2);
    p1 += __shfl_xor_sync(0xffffffff, p1, 2);
    p0 += __shfl_xor_sync(0xffffffff, p0, 4);
    p1 += __shfl_xor_sync(0xffffffff, p1, 4);

    float ex0 = __expf(p0 * 0.1767766952966369f);   // heads at lanes 0,8,16,24
    float ex1 = __expf(p1 * 0.1767766952966369f);

    float a0 = __shfl_sync(0xffffffff, ex0, 0);
    float a1 = __shfl_sync(0xffffffff, ex0, 8);
    float a2 = __shfl_sync(0xffffffff, ex0, 16);
    float a3 = __shfl_sync(0xffffffff, ex0, 24);
    float b0 = __shfl_sync(0xffffffff, ex1, 0);
    float b1 = __shfl_sync(0xffffffff, ex1, 8);
    float b2 = __shfl_sync(0xffffffff, ex1, 16);
    float b3 = __shfl_sync(0xffffffff, ex1, 24);

    if (lane == 0) {
        int pos = atomicAdd(&g_cursor[dd.x], 1);
        if (pos < MAXDEG) {
            int slot = (dd.x << 7) + pos;
            g_e_idx[slot] = rr.x * N_NODES + ss.x;
            g_e_score[slot] = make_float4(a0, a1, a2, a3);
        }
    } else if (lane == 1) {
        int pos = atomicAdd(&g_cursor[dd.y], 1);
        if (pos < MAXDEG) {
            int slot = (dd.y << 7) + pos;
            g_e_idx[slot] = rr.y * N_NODES + ss.y;
            g_e_score[slot] = make_float4(b0, b1, b2, b3);
        }
    }
}

// Per-destination-node softmax + weighted aggregation. Block (128 thr) per node.
// (R9 measured form: two passes, all-warp denominator, simple gather loop.)
__global__ void __launch_bounds__(128) agg_kernel()
{
    int n = blockIdx.x;
    int tid = threadIdx.x;
    int deg = min(g_cursor[n], MAXDEG);
    int base = n << 7;

    __shared__ float s_den[R_T * H_H];
    __shared__ float s_inv[R_T * H_H];
    __shared__ int    s_i[32];
    __shared__ float4 s_a[32];

    if (tid < R_T * H_H) s_den[tid] = 0.f;
    __syncthreads();
    if (tid == 0) g_cursor[n] = 0;   // reset for next replay (deg already read)

    for (int j = tid; j < deg; j += 128) {
        int r = g_e_idx[base + j] >> 14;        // N = 2^14
        float4 sc = g_e_score[base + j];
        atomicAdd(&s_den[r * 4 + 0], sc.x);
        atomicAdd(&s_den[r * 4 + 1], sc.y);
        atomicAdd(&s_den[r * 4 + 2], sc.z);
        atomicAdd(&s_den[r * 4 + 3], sc.w);
    }
    __syncthreads();
    if (tid < R_T * H_H) s_inv[tid] = 1.0f / s_den[tid];
    __syncthreads();

    float a0 = 0.f, a1 = 0.f, a2 = 0.f, a3 = 0.f;
    for (int j0 = 0; j0 < deg; j0 += 32) {
        int m = min(32, deg - j0);
        if (tid < m) {
            int idx = g_e_idx[base + j0 + tid];
            int r = idx >> 14;
            float4 sc = g_e_score[base + j0 + tid];
            float4 a;
            a.x = sc.x * s_inv[r * 4 + 0];
            a.y = sc.y * s_inv[r * 4 + 1];
            a.z = sc.z * s_inv[r * 4 + 2];
            a.w = sc.w * s_inv[r * 4 + 3];
            s_a[tid] = a;
            s_i[tid] = idx;
        }
        __syncthreads();
        for (int jj = 0; jj < m; jj++) {
            int vrow = s_i[jj];
            float4 a = s_a[jj];
            float v = g_V[(size_t)vrow * D + tid];
            a0 += a.x * v; a1 += a.y * v; a2 += a.z * v; a3 += a.w * v;
        }
        __syncthreads();
    }

    float* o = g_agg + (size_t)n * 512;
    o[tid]       = a0;
    o[128 + tid] = a1;
    o[256 + tid] = a2;
    o[384 + tid] = a3;
}

// Final projection (tensor-core): out[N,128] = g_agg[N,512] @ Wt[512,128] + bt.
__global__ void __launch_bounds__(512) final_gemm_tc(
    const float* __restrict__ Wt, const float* __restrict__ bt,
    float* __restrict__ out)
{
    extern __shared__ float smem[];
    float* h_s = smem;
    float* w_s = smem + 16384;

    int nodeBase = blockIdx.x * 128;
    int tid = threadIdx.x;
    int lane = tid & 31, wid = tid >> 5;
    int gid = lane >> 2, tig = lane & 3;
    int wrow = wid & 7, wcol = wid >> 3;
    int cbase = wcol * 64;
    int nA = wrow * 16 + gid;
    int xrA = gid << 2;

    const uint32_t* hsu = (const uint32_t*)h_s;
    const uint32_t* wsu = (const uint32_t*)w_s;

    float acc[8][4];
    #pragma unroll
    for (int nt = 0; nt < 8; nt++) {
        float2 bv2 = *(const float2*)(bt + cbase + nt * 8 + 2 * tig);
        acc[nt][0] = bv2.x; acc[nt][1] = bv2.y;
        acc[nt][2] = bv2.x; acc[nt][3] = bv2.y;
    }

    #pragma unroll 1
    for (int kb = 0; kb < 4; kb++) {
        __syncthreads();
        stage_A(h_s, (const float4*)g_agg, 128, nodeBase, kb * 32, tid);
        stage_B(w_s, (const float4*)Wt, kb * 128, tid);
        __syncthreads();
        mma_tile(hsu, wsu, nA, xrA, cbase, gid, tig, acc);
    }

    int row0 = nodeBase + wrow * 16 + gid;
    #pragma unroll
    for (int nt = 0; nt < 8; nt++) {
        int col0 = cbase + nt * 8 + 2 * tig;
        *(float2*)(out + (size_t)row0 * D + col0) =
            make_float2(acc[nt][0], acc[nt][1]);
        *(float2*)(out + (size_t)(row0 + 8) * D + col0) =
            make_float2(acc[nt][2], acc[nt][3]);
    }
}

// ---------------- launch ----------------
extern "C" void kernel_launch(void* const* d_in, const int* in_sizes, int n_in,
                              void* d_out, int out_size)
{
    const float* h  = (const float*)d_in[0];
    const float* Wk = (const float*)d_in[1];
    const float* bk = (const float*)d_in[2];
    const float* Wq = (const float*)d_in[3];
    const float* bq = (const float*)d_in[4];
    const float* Wv = (const float*)d_in[5];
    const float* bv = (const float*)d_in[6];
    const float* Wt = (const float*)d_in[7];
    const float* bt = (const float*)d_in[8];
    const int* src   = (const int*)d_in[9];
    const int* dst   = (const int*)d_in[10];
    const int* etype = (const int*)d_in[11];
    float* out = (float*)d_out;

    const int TC_SMEM = 2 * 128 * 128 * 4;  // 128 KB dynamic
    cudaFuncSetAttribute(qkv_gemm_tc,
                         cudaFuncAttributeMaxDynamicSharedMemorySize, TC_SMEM);
    cudaFuncSetAttribute(final_gemm_tc,
                         cudaFuncAttributeMaxDynamicSharedMemorySize, TC_SMEM);

    qkv_gemm_tc<<<dim3(N_NODES / 128, R_T), 512, TC_SMEM>>>(h, Wk, bk, Wq, bq, Wv, bv); // 1
    score_kernel<<<E_EDGES / 16, 256>>>(src, dst, etype);         // 2
    agg_kernel<<<N_NODES, 128>>>();                               // 3
    final_gemm_tc<<<N_NODES / 128, 512, TC_SMEM>>>(Wt, bt, out);  // 4 (profiled)
}